// round 1
// baseline (speedup 1.0000x reference)
#include <cuda_runtime.h>
#include <cuda_bf16.h>

#define Bsz 4
#define Sq  2048
#define Dm  1024
#define Hh  16
#define Dh  64
#define Tt  (Bsz * Sq)   /* 8192 tokens */

// Scratch (allocation-free per harness rules): Q,K,V,Z each (T, H*Dh) fp32
__device__ float g_Q[(size_t)Tt * Dm];
__device__ float g_K[(size_t)Tt * Dm];
__device__ float g_V[(size_t)Tt * Dm];
__device__ float g_Z[(size_t)Tt * Dm];

// ---------------------------------------------------------------------------
// QKV projection GEMM: out[t, h*64+e] = sum_d x[t,d] * W[h,d,e] + b[h,e]
// Tile: BM=128, BN=64 (one head), BK=16. 256 threads, 8x4 micro-tile.
// grid = (Tt/128, 3*Hh)
// ---------------------------------------------------------------------------
__global__ __launch_bounds__(256) void qkv_gemm(
    const float* __restrict__ x,
    const float* __restrict__ wq, const float* __restrict__ bq,
    const float* __restrict__ wk, const float* __restrict__ bk,
    const float* __restrict__ wv, const float* __restrict__ bv)
{
    __shared__ float As[16][128];
    __shared__ float Bs[16][64];

    const int j    = blockIdx.y;           // 0..47
    const int proj = j >> 4;
    const int h    = j & 15;
    const float* W    = (proj == 0 ? wq : proj == 1 ? wk : wv) + (size_t)h * Dm * Dh;
    const float* bias = (proj == 0 ? bq : proj == 1 ? bk : bv) + h * Dh;
    float* C = (proj == 0 ? g_Q : proj == 1 ? g_K : g_V);

    const int m0  = blockIdx.x * 128;
    const int tid = threadIdx.x;
    const int tx  = tid & 15, ty = tid >> 4;
    const int ar  = tid >> 2, ak = (tid & 3) * 4;

    float acc[8][4];
    #pragma unroll
    for (int i = 0; i < 8; i++)
        #pragma unroll
        for (int jj = 0; jj < 4; jj++) acc[i][jj] = 0.f;

    for (int k0 = 0; k0 < Dm; k0 += 16) {
        #pragma unroll
        for (int i = 0; i < 2; i++) {
            float4 v = *(const float4*)(x + (size_t)(m0 + ar + i * 64) * Dm + k0 + ak);
            As[ak + 0][ar + i * 64] = v.x;
            As[ak + 1][ar + i * 64] = v.y;
            As[ak + 2][ar + i * 64] = v.z;
            As[ak + 3][ar + i * 64] = v.w;
        }
        *(float4*)&Bs[ty][tx * 4] = *(const float4*)(W + (size_t)(k0 + ty) * Dh + tx * 4);
        __syncthreads();
        #pragma unroll
        for (int k = 0; k < 16; k++) {
            float a[8], bfr[4];
            *(float4*)(a)     = *(const float4*)&As[k][ty * 8];
            *(float4*)(a + 4) = *(const float4*)&As[k][ty * 8 + 4];
            *(float4*)(bfr)   = *(const float4*)&Bs[k][tx * 4];
            #pragma unroll
            for (int i = 0; i < 8; i++)
                #pragma unroll
                for (int jj = 0; jj < 4; jj++)
                    acc[i][jj] += a[i] * bfr[jj];
        }
        __syncthreads();
    }

    float bb[4];
    #pragma unroll
    for (int jj = 0; jj < 4; jj++) bb[jj] = bias[tx * 4 + jj];
    #pragma unroll
    for (int i = 0; i < 8; i++) {
        float4 v = make_float4(acc[i][0] + bb[0], acc[i][1] + bb[1],
                               acc[i][2] + bb[2], acc[i][3] + bb[3]);
        *(float4*)(C + (size_t)(m0 + ty * 8 + i) * Dm + h * Dh + tx * 4) = v;
    }
}

// ---------------------------------------------------------------------------
// Output projection GEMM: out[t, n] = sum_k z[t,k] * W_O_flat[k,n] + b_O[n]
// W_O (H, DH, D) flattened over (h,e) matches z's k = h*64+e layout exactly.
// grid = (Tt/128, Dm/64)
// ---------------------------------------------------------------------------
__global__ __launch_bounds__(256) void out_gemm(
    const float* __restrict__ wo, const float* __restrict__ bo,
    float* __restrict__ out)
{
    __shared__ float As[16][128];
    __shared__ float Bs[16][64];

    const int n0  = blockIdx.y * 64;
    const int m0  = blockIdx.x * 128;
    const int tid = threadIdx.x;
    const int tx  = tid & 15, ty = tid >> 4;
    const int ar  = tid >> 2, ak = (tid & 3) * 4;

    float acc[8][4];
    #pragma unroll
    for (int i = 0; i < 8; i++)
        #pragma unroll
        for (int jj = 0; jj < 4; jj++) acc[i][jj] = 0.f;

    for (int k0 = 0; k0 < Dm; k0 += 16) {
        #pragma unroll
        for (int i = 0; i < 2; i++) {
            float4 v = *(const float4*)(g_Z + (size_t)(m0 + ar + i * 64) * Dm + k0 + ak);
            As[ak + 0][ar + i * 64] = v.x;
            As[ak + 1][ar + i * 64] = v.y;
            As[ak + 2][ar + i * 64] = v.z;
            As[ak + 3][ar + i * 64] = v.w;
        }
        *(float4*)&Bs[ty][tx * 4] = *(const float4*)(wo + (size_t)(k0 + ty) * Dm + n0 + tx * 4);
        __syncthreads();
        #pragma unroll
        for (int k = 0; k < 16; k++) {
            float a[8], bfr[4];
            *(float4*)(a)     = *(const float4*)&As[k][ty * 8];
            *(float4*)(a + 4) = *(const float4*)&As[k][ty * 8 + 4];
            *(float4*)(bfr)   = *(const float4*)&Bs[k][tx * 4];
            #pragma unroll
            for (int i = 0; i < 8; i++)
                #pragma unroll
                for (int jj = 0; jj < 4; jj++)
                    acc[i][jj] += a[i] * bfr[jj];
        }
        __syncthreads();
    }

    float bb[4];
    #pragma unroll
    for (int jj = 0; jj < 4; jj++) bb[jj] = bo[n0 + tx * 4 + jj];
    #pragma unroll
    for (int i = 0; i < 8; i++) {
        float4 v = make_float4(acc[i][0] + bb[0], acc[i][1] + bb[1],
                               acc[i][2] + bb[2], acc[i][3] + bb[3]);
        *(float4*)(out + (size_t)(m0 + ty * 8 + i) * Dm + n0 + tx * 4) = v;
    }
}

// ---------------------------------------------------------------------------
// Flash attention: per (b, h, q-tile of 64) process k-tiles 0..qb with online
// softmax. 256 threads = 16x16 grid, each thread owns a 4x4 micro-tile.
// Dynamic smem: Qt[e][q], Kt[e][k] (transposed for GEMM-style reads),
// Vs[k][e], Ps[q][k]. 4 * 64*64*4B = 64 KB.
// grid = (Sq/64, Hh, Bsz)
// ---------------------------------------------------------------------------
__global__ __launch_bounds__(256) void attn_kernel()
{
    extern __shared__ float sm[];
    float (*Qt)[64] = (float (*)[64])(sm);
    float (*Kt)[64] = (float (*)[64])(sm + 64 * 64);
    float (*Vs)[64] = (float (*)[64])(sm + 2 * 64 * 64);
    float (*Ps)[64] = (float (*)[64])(sm + 3 * 64 * 64);

    const int qb = blockIdx.x, h = blockIdx.y, b = blockIdx.z;
    const int tid = threadIdx.x;
    const int tx = tid & 15, ty = tid >> 4;
    const int lr = tid >> 2;             // 0..63 (tile row for loads)
    const int le = (tid & 3) * 16;       // e-offset base for loads

    // Load Q tile transposed with 1/sqrt(DH) folded in
    const float* Qg = g_Q + ((size_t)(b * Sq + qb * 64) * Hh + h) * Dh;
    #pragma unroll
    for (int i = 0; i < 4; i++) {
        float4 v = *(const float4*)(Qg + (size_t)lr * Dm + le + i * 4);
        Qt[le + i * 4 + 0][lr] = v.x * 0.125f;
        Qt[le + i * 4 + 1][lr] = v.y * 0.125f;
        Qt[le + i * 4 + 2][lr] = v.z * 0.125f;
        Qt[le + i * 4 + 3][lr] = v.w * 0.125f;
    }

    float o[4][4];
    float m[4], l[4];
    #pragma unroll
    for (int r = 0; r < 4; r++) {
        m[r] = -1e30f; l[r] = 0.f;
        #pragma unroll
        for (int c = 0; c < 4; c++) o[r][c] = 0.f;
    }

    for (int kt = 0; kt <= qb; kt++) {
        __syncthreads();   // previous iteration's PV reads of Kt/Vs/Ps done
        const float* Kg = g_K + ((size_t)(b * Sq + kt * 64) * Hh + h) * Dh;
        const float* Vg = g_V + ((size_t)(b * Sq + kt * 64) * Hh + h) * Dh;
        #pragma unroll
        for (int i = 0; i < 4; i++) {
            float4 v = *(const float4*)(Kg + (size_t)lr * Dm + le + i * 4);
            Kt[le + i * 4 + 0][lr] = v.x;
            Kt[le + i * 4 + 1][lr] = v.y;
            Kt[le + i * 4 + 2][lr] = v.z;
            Kt[le + i * 4 + 3][lr] = v.w;
            float4 w = *(const float4*)(Vg + (size_t)lr * Dm + le + i * 4);
            *(float4*)&Vs[lr][le + i * 4] = w;
        }
        __syncthreads();

        // S = (Q/8) K^T, 4x4 per thread
        float s[4][4];
        #pragma unroll
        for (int r = 0; r < 4; r++)
            #pragma unroll
            for (int c = 0; c < 4; c++) s[r][c] = 0.f;
        #pragma unroll 8
        for (int e = 0; e < 64; e++) {
            float a[4], k4[4];
            *(float4*)a  = *(const float4*)&Qt[e][ty * 4];
            *(float4*)k4 = *(const float4*)&Kt[e][tx * 4];
            #pragma unroll
            for (int r = 0; r < 4; r++)
                #pragma unroll
                for (int c = 0; c < 4; c++)
                    s[r][c] += a[r] * k4[c];
        }

        // Causal mask (only relevant on diagonal tile; local indices suffice)
        if (kt == qb) {
            #pragma unroll
            for (int r = 0; r < 4; r++)
                #pragma unroll
                for (int c = 0; c < 4; c++)
                    if (tx * 4 + c > ty * 4 + r) s[r][c] = -1e30f;
        }

        // Row max over the 16-thread row group (lanes 0-15 / 16-31 per ty)
        float rmax[4], rsum[4];
        #pragma unroll
        for (int r = 0; r < 4; r++)
            rmax[r] = fmaxf(fmaxf(s[r][0], s[r][1]), fmaxf(s[r][2], s[r][3]));
        #pragma unroll
        for (int off = 1; off < 16; off <<= 1)
            #pragma unroll
            for (int r = 0; r < 4; r++)
                rmax[r] = fmaxf(rmax[r], __shfl_xor_sync(0xffffffffu, rmax[r], off));

        #pragma unroll
        for (int r = 0; r < 4; r++) {
            float mn = fmaxf(m[r], rmax[r]);
            float sc = __expf(m[r] - mn);
            m[r] = mn;
            #pragma unroll
            for (int c = 0; c < 4; c++) s[r][c] = __expf(s[r][c] - mn);
            rsum[r] = (s[r][0] + s[r][1]) + (s[r][2] + s[r][3]);
            l[r] *= sc;
            #pragma unroll
            for (int c = 0; c < 4; c++) o[r][c] *= sc;
        }
        #pragma unroll
        for (int off = 1; off < 16; off <<= 1)
            #pragma unroll
            for (int r = 0; r < 4; r++)
                rsum[r] += __shfl_xor_sync(0xffffffffu, rsum[r], off);
        #pragma unroll
        for (int r = 0; r < 4; r++) l[r] += rsum[r];

        // Stage P to smem for the PV GEMM
        #pragma unroll
        for (int r = 0; r < 4; r++)
            *(float4*)&Ps[ty * 4 + r][tx * 4] =
                make_float4(s[r][0], s[r][1], s[r][2], s[r][3]);
        __syncthreads();

        // O += P * V
        #pragma unroll 4
        for (int k0 = 0; k0 < 64; k0 += 4) {
            float p[4][4];
            #pragma unroll
            for (int r = 0; r < 4; r++)
                *(float4*)p[r] = *(const float4*)&Ps[ty * 4 + r][k0];
            #pragma unroll
            for (int kk = 0; kk < 4; kk++) {
                float v4[4];
                *(float4*)v4 = *(const float4*)&Vs[k0 + kk][tx * 4];
                #pragma unroll
                for (int r = 0; r < 4; r++)
                    #pragma unroll
                    for (int c = 0; c < 4; c++)
                        o[r][c] += p[r][kk] * v4[c];
            }
        }
    }

    // Normalize and write z
    float* Zg = g_Z + ((size_t)(b * Sq + qb * 64) * Hh + h) * Dh;
    #pragma unroll
    for (int r = 0; r < 4; r++) {
        float inv = 1.f / l[r];
        float4 v = make_float4(o[r][0] * inv, o[r][1] * inv,
                               o[r][2] * inv, o[r][3] * inv);
        *(float4*)(Zg + (size_t)(ty * 4 + r) * Dm + tx * 4) = v;
    }
}

// ---------------------------------------------------------------------------
extern "C" void kernel_launch(void* const* d_in, const int* in_sizes, int n_in,
                              void* d_out, int out_size)
{
    const float* x  = (const float*)d_in[0];
    const float* wq = (const float*)d_in[1];
    const float* bq = (const float*)d_in[2];
    const float* wk = (const float*)d_in[3];
    const float* bk = (const float*)d_in[4];
    const float* wv = (const float*)d_in[5];
    const float* bv = (const float*)d_in[6];
    const float* wo = (const float*)d_in[7];
    const float* bo = (const float*)d_in[8];
    float* out = (float*)d_out;

    cudaFuncSetAttribute(attn_kernel,
                         cudaFuncAttributeMaxDynamicSharedMemorySize, 65536);

    qkv_gemm<<<dim3(Tt / 128, 48), 256>>>(x, wq, bq, wk, bk, wv, bv);
    attn_kernel<<<dim3(Sq / 64, Hh, Bsz), 256, 65536>>>();
    out_gemm<<<dim3(Tt / 128, Dm / 64), 256>>>(wo, bo, out);
}

// round 3
// speedup vs baseline: 1.2570x; 1.2570x over previous
#include <cuda_runtime.h>
#include <cuda_bf16.h>
#include <cstdint>

#define Bsz 4
#define Sq  2048
#define Dm  1024
#define Hh  16
#define Dh  64
#define Tt  (Bsz * Sq)   /* 8192 tokens */

// ---------------------------------------------------------------------------
// Scratch (__device__ globals; allocation-free per harness rules)
// ---------------------------------------------------------------------------
__device__ float g_Q[(size_t)Tt * Dm];
__device__ float g_K[(size_t)Tt * Dm];
__device__ float g_V[(size_t)Tt * Dm];
__device__ float g_Z[(size_t)Tt * Dm];

// bf16 split-precision staging
__device__ __nv_bfloat16 g_xh[(size_t)Tt * Dm];
__device__ __nv_bfloat16 g_xl[(size_t)Tt * Dm];
__device__ __nv_bfloat16 g_zh[(size_t)Tt * Dm];
__device__ __nv_bfloat16 g_zl[(size_t)Tt * Dm];
__device__ __nv_bfloat16 g_wh[(size_t)3 * Dm * Dm];  // QKV weights, [n=3072][k=1024]
__device__ __nv_bfloat16 g_wl[(size_t)3 * Dm * Dm];
__device__ __nv_bfloat16 g_oh[(size_t)Dm * Dm];      // W_O transposed, [n=1024][k=1024]
__device__ __nv_bfloat16 g_ol[(size_t)Dm * Dm];

// ---------------------------------------------------------------------------
// PTX helpers — ONLY arch-stable features (mma.sync sm_80, ldmatrix sm_75,
// cp.async sm_80). No tcgen05/TMA: harness PTX target is sm_103 (no 'a').
// ---------------------------------------------------------------------------
__device__ __forceinline__ uint32_t smem_u32(const void* p) {
    uint32_t a;
    asm("{ .reg .u64 t; cvta.to.shared.u64 t, %1; cvt.u32.u64 %0, t; }" : "=r"(a) : "l"(p));
    return a;
}
#define CP_ASYNC16(dst, src) \
    asm volatile("cp.async.cg.shared.global [%0], [%1], 16;" :: "r"(dst), "l"(src))
#define CP_COMMIT() asm volatile("cp.async.commit_group;" ::: "memory")
#define CP_WAIT1()  asm volatile("cp.async.wait_group 1;" ::: "memory")
#define CP_WAIT0()  asm volatile("cp.async.wait_group 0;" ::: "memory")

__device__ __forceinline__ void ldmat4(uint32_t r[4], uint32_t addr) {
    asm volatile("ldmatrix.sync.aligned.m8n8.x4.shared.b16 {%0,%1,%2,%3}, [%4];"
                 : "=r"(r[0]), "=r"(r[1]), "=r"(r[2]), "=r"(r[3]) : "r"(addr));
}
__device__ __forceinline__ void mma16816(float* c, const uint32_t* a,
                                         uint32_t b0, uint32_t b1) {
    asm volatile("mma.sync.aligned.m16n8k16.row.col.f32.bf16.bf16.f32 "
                 "{%0,%1,%2,%3}, {%4,%5,%6,%7}, {%8,%9}, {%0,%1,%2,%3};"
                 : "+f"(c[0]), "+f"(c[1]), "+f"(c[2]), "+f"(c[3])
                 : "r"(a[0]), "r"(a[1]), "r"(a[2]), "r"(a[3]), "r"(b0), "r"(b1));
}

// ---------------------------------------------------------------------------
// Prep: split fp32 -> bf16 hi/lo
// ---------------------------------------------------------------------------
__global__ void conv_split(const float* __restrict__ in, __nv_bfloat16* __restrict__ hi,
                           __nv_bfloat16* __restrict__ lo, int n4)
{
    int i = blockIdx.x * blockDim.x + threadIdx.x;
    if (i >= n4) return;
    float4 v = ((const float4*)in)[i];
    __nv_bfloat16 h0 = __float2bfloat16(v.x), h1 = __float2bfloat16(v.y);
    __nv_bfloat16 h2 = __float2bfloat16(v.z), h3 = __float2bfloat16(v.w);
    __nv_bfloat16 l0 = __float2bfloat16(v.x - __bfloat162float(h0));
    __nv_bfloat16 l1 = __float2bfloat16(v.y - __bfloat162float(h1));
    __nv_bfloat16 l2 = __float2bfloat16(v.z - __bfloat162float(h2));
    __nv_bfloat16 l3 = __float2bfloat16(v.w - __bfloat162float(h3));
    ((__nv_bfloat162*)hi)[2 * i]     = __nv_bfloat162(h0, h1);
    ((__nv_bfloat162*)hi)[2 * i + 1] = __nv_bfloat162(h2, h3);
    ((__nv_bfloat162*)lo)[2 * i]     = __nv_bfloat162(l0, l1);
    ((__nv_bfloat162*)lo)[2 * i + 1] = __nv_bfloat162(l2, l3);
}

// QKV weights -> [n=3072][k=1024] bf16 hi/lo, n = proj*1024 + h*64 + e, k = d
__global__ void conv_wqkv(const float* __restrict__ wq, const float* __restrict__ wk,
                          const float* __restrict__ wv)
{
    int id = blockIdx.x * 256 + threadIdx.x;
    if (id >= 3 * Dm * Dm) return;
    int n = id >> 10, d = id & 1023;
    int proj = n >> 10, nl = n & 1023, h = nl >> 6, e = nl & 63;
    const float* W = (proj == 0 ? wq : proj == 1 ? wk : wv);
    float v = W[((size_t)h * Dm + d) * Dh + e];
    __nv_bfloat16 hh = __float2bfloat16(v);
    g_wh[id] = hh;
    g_wl[id] = __float2bfloat16(v - __bfloat162float(hh));
}

// W_O (H, DH, D) -> [n=d_out][k=h*64+e] bf16 hi/lo
__global__ void conv_wo(const float* __restrict__ wo)
{
    int id = blockIdx.x * 256 + threadIdx.x;
    if (id >= Dm * Dm) return;
    int n = id >> 10, k = id & 1023;
    float v = wo[(size_t)k * Dm + n];
    __nv_bfloat16 hh = __float2bfloat16(v);
    g_oh[id] = hh;
    g_ol[id] = __float2bfloat16(v - __bfloat162float(hh));
}

// ---------------------------------------------------------------------------
// HMMA bf16x3 GEMM: C[m][n] = sum_k A[m][k]*B[n][k] + bias[n]
// CTA tile 128x128x32, 8 warps (2x4), warp tile 64x32.
// Smem: tile-contiguous (each 8x8 bf16 tile = 128 contiguous bytes) so
// ldmatrix.x4 reads are conflict-free. Double buffered via cp.async.
// grid = (M/128, N/128). For QKV, N-tile selects proj via n0>>10.
// ---------------------------------------------------------------------------
#define ARR_BYTES 8192                 /* 128x32 bf16 */
#define BUF_BYTES (4 * ARR_BYTES)      /* Ah, Al, Bh, Bl */
#define GEMM_SMEM (2 * BUF_BYTES)      /* 65536 */

__global__ __launch_bounds__(256) void hmma_gemm(
    const __nv_bfloat16* __restrict__ Ah, const __nv_bfloat16* __restrict__ Al,
    const __nv_bfloat16* __restrict__ Bh, const __nv_bfloat16* __restrict__ Bl,
    const float* __restrict__ b0, const float* __restrict__ b1,
    const float* __restrict__ b2,
    float* __restrict__ C0, float* __restrict__ C1, float* __restrict__ C2)
{
    extern __shared__ char smc[];
    const uint32_t sb = smem_u32(smc);
    const int tid = threadIdx.x, wid = tid >> 5, lane = tid & 31;
    const int warp_m = wid >> 2, warp_n = wid & 3;
    const int g = lane >> 3, r = lane & 7;
    const int m0  = blockIdx.x * 128;
    const int n0g = blockIdx.y * 128;
    const int proj = n0g >> 10;
    const int nl   = n0g & 1023;
    const float* bias = (proj == 0 ? b0 : proj == 1 ? b1 : b2);
    float* C = (proj == 0 ? C0 : proj == 1 ? C1 : C2);

    const __nv_bfloat16* srcs[4];
    srcs[0] = Ah + (size_t)m0  * Dm;
    srcs[1] = Al + (size_t)m0  * Dm;
    srcs[2] = Bh + (size_t)n0g * Dm;
    srcs[3] = Bl + (size_t)n0g * Dm;

    // per-lane ldmatrix address constants (tile-contiguous layout)
    // A frag (mi, ks): off = ((warp_m*8 + mi*2 + (g&1))*4 + 2*ks + (g>>1))*128 + r*16
    // B frag (np, ks): off = ((warp_n*4 + np*2 + (g>>1))*4 + 2*ks + (g&1))*128 + r*16
    const uint32_t aoff0 = (uint32_t)(((warp_m * 8 + (g & 1)) * 4 + (g >> 1)) * 128 + r * 16);
    const uint32_t boff0 = (uint32_t)(((warp_n * 4 + (g >> 1)) * 4 + (g & 1)) * 128 + r * 16);

    auto fill = [&](int buf, int k0) {
        #pragma unroll
        for (int arr = 0; arr < 4; arr++) {
            uint32_t abase = sb + buf * BUF_BYTES + arr * ARR_BYTES;
            const __nv_bfloat16* s = srcs[arr];
            #pragma unroll
            for (int i = 0; i < 2; i++) {
                int cid = tid + 256 * i;
                int row = cid >> 2, kc = (cid & 3) * 8;
                const void* gsrc = s + (size_t)row * Dm + k0 + kc;
                uint32_t soff = abase + (uint32_t)(((row >> 3) * 4 + (kc >> 3)) * 128
                                                   + (row & 7) * 16);
                CP_ASYNC16(soff, gsrc);
            }
        }
    };

    float acc[4][4][4];
    #pragma unroll
    for (int mi = 0; mi < 4; mi++)
        #pragma unroll
        for (int nj = 0; nj < 4; nj++)
            #pragma unroll
            for (int c = 0; c < 4; c++) acc[mi][nj][c] = 0.f;

    fill(0, 0);
    CP_COMMIT();

    const int NIT = Dm / 32;   // 32 slabs
    for (int it = 0; it < NIT; it++) {
        if (it + 1 < NIT) { fill((it + 1) & 1, (it + 1) * 32); CP_COMMIT(); CP_WAIT1(); }
        else              { CP_WAIT0(); }
        __syncthreads();

        const uint32_t bufb = sb + (it & 1) * BUF_BYTES;
        const uint32_t bAh = bufb, bAl = bufb + ARR_BYTES;
        const uint32_t bBh = bufb + 2 * ARR_BYTES, bBl = bufb + 3 * ARR_BYTES;

        uint32_t afr[2][4][4];
        // ---- load Ah fragments (both k-steps, 4 m-tiles) ----
        #pragma unroll
        for (int ks = 0; ks < 2; ks++)
            #pragma unroll
            for (int mi = 0; mi < 4; mi++)
                ldmat4(afr[ks][mi], bAh + aoff0 + mi * 1024 + ks * 256);
        // ---- pass 1: Ah x Bh; pass 2: Ah x Bl ----
        #pragma unroll
        for (int pb = 0; pb < 2; pb++) {
            const uint32_t bB = pb ? bBl : bBh;
            #pragma unroll
            for (int ks = 0; ks < 2; ks++) {
                uint32_t bb[2][4];
                ldmat4(bb[0], bB + boff0 + ks * 256);
                ldmat4(bb[1], bB + boff0 + 1024 + ks * 256);
                #pragma unroll
                for (int mi = 0; mi < 4; mi++)
                    #pragma unroll
                    for (int nj = 0; nj < 4; nj++)
                        mma16816(acc[mi][nj], afr[ks][mi],
                                 bb[nj >> 1][(nj & 1) * 2], bb[nj >> 1][(nj & 1) * 2 + 1]);
            }
        }
        // ---- pass 3: Al x Bh ----
        #pragma unroll
        for (int ks = 0; ks < 2; ks++)
            #pragma unroll
            for (int mi = 0; mi < 4; mi++)
                ldmat4(afr[ks][mi], bAl + aoff0 + mi * 1024 + ks * 256);
        #pragma unroll
        for (int ks = 0; ks < 2; ks++) {
            uint32_t bb[2][4];
            ldmat4(bb[0], bBh + boff0 + ks * 256);
            ldmat4(bb[1], bBh + boff0 + 1024 + ks * 256);
            #pragma unroll
            for (int mi = 0; mi < 4; mi++)
                #pragma unroll
                for (int nj = 0; nj < 4; nj++)
                    mma16816(acc[mi][nj], afr[ks][mi],
                             bb[nj >> 1][(nj & 1) * 2], bb[nj >> 1][(nj & 1) * 2 + 1]);
        }
        __syncthreads();
    }

    // ---- epilogue: bias + direct fp32 stores ----
    const int gq = lane >> 2, tq = lane & 3;
    #pragma unroll
    for (int mi = 0; mi < 4; mi++) {
        const int row = m0 + warp_m * 64 + mi * 16 + gq;
        #pragma unroll
        for (int nj = 0; nj < 4; nj++) {
            const int col = nl + warp_n * 32 + nj * 8 + tq * 2;
            const float bv0 = bias[col], bv1 = bias[col + 1];
            float2 v0 = make_float2(acc[mi][nj][0] + bv0, acc[mi][nj][1] + bv1);
            float2 v1 = make_float2(acc[mi][nj][2] + bv0, acc[mi][nj][3] + bv1);
            *(float2*)(C + (size_t)row * Dm + col)       = v0;
            *(float2*)(C + (size_t)(row + 8) * Dm + col) = v1;
        }
    }
}

// ---------------------------------------------------------------------------
// Flash attention (SIMT fp32, unchanged from passing round)
// ---------------------------------------------------------------------------
__global__ __launch_bounds__(256) void attn_kernel()
{
    extern __shared__ float sm[];
    float (*Qt)[64] = (float (*)[64])(sm);
    float (*Kt)[64] = (float (*)[64])(sm + 64 * 64);
    float (*Vs)[64] = (float (*)[64])(sm + 2 * 64 * 64);
    float (*Ps)[64] = (float (*)[64])(sm + 3 * 64 * 64);

    const int qb = blockIdx.x, h = blockIdx.y, b = blockIdx.z;
    const int tid = threadIdx.x;
    const int tx = tid & 15, ty = tid >> 4;
    const int lr = tid >> 2;
    const int le = (tid & 3) * 16;

    const float* Qg = g_Q + (size_t)(b * Sq + qb * 64) * Dm + h * Dh;
    #pragma unroll
    for (int i = 0; i < 4; i++) {
        float4 v = *(const float4*)(Qg + (size_t)lr * Dm + le + i * 4);
        Qt[le + i * 4 + 0][lr] = v.x * 0.125f;
        Qt[le + i * 4 + 1][lr] = v.y * 0.125f;
        Qt[le + i * 4 + 2][lr] = v.z * 0.125f;
        Qt[le + i * 4 + 3][lr] = v.w * 0.125f;
    }

    float o[4][4];
    float m[4], l[4];
    #pragma unroll
    for (int r = 0; r < 4; r++) {
        m[r] = -1e30f; l[r] = 0.f;
        #pragma unroll
        for (int c = 0; c < 4; c++) o[r][c] = 0.f;
    }

    for (int kt = 0; kt <= qb; kt++) {
        __syncthreads();
        const float* Kg = g_K + (size_t)(b * Sq + kt * 64) * Dm + h * Dh;
        const float* Vg = g_V + (size_t)(b * Sq + kt * 64) * Dm + h * Dh;
        #pragma unroll
        for (int i = 0; i < 4; i++) {
            float4 v = *(const float4*)(Kg + (size_t)lr * Dm + le + i * 4);
            Kt[le + i * 4 + 0][lr] = v.x;
            Kt[le + i * 4 + 1][lr] = v.y;
            Kt[le + i * 4 + 2][lr] = v.z;
            Kt[le + i * 4 + 3][lr] = v.w;
            float4 w = *(const float4*)(Vg + (size_t)lr * Dm + le + i * 4);
            *(float4*)&Vs[lr][le + i * 4] = w;
        }
        __syncthreads();

        float s[4][4];
        #pragma unroll
        for (int r = 0; r < 4; r++)
            #pragma unroll
            for (int c = 0; c < 4; c++) s[r][c] = 0.f;
        #pragma unroll 8
        for (int e = 0; e < 64; e++) {
            float a[4], k4[4];
            *(float4*)a  = *(const float4*)&Qt[e][ty * 4];
            *(float4*)k4 = *(const float4*)&Kt[e][tx * 4];
            #pragma unroll
            for (int r = 0; r < 4; r++)
                #pragma unroll
                for (int c = 0; c < 4; c++)
                    s[r][c] += a[r] * k4[c];
        }

        if (kt == qb) {
            #pragma unroll
            for (int r = 0; r < 4; r++)
                #pragma unroll
                for (int c = 0; c < 4; c++)
                    if (tx * 4 + c > ty * 4 + r) s[r][c] = -1e30f;
        }

        float rmax[4], rsum[4];
        #pragma unroll
        for (int r = 0; r < 4; r++)
            rmax[r] = fmaxf(fmaxf(s[r][0], s[r][1]), fmaxf(s[r][2], s[r][3]));
        #pragma unroll
        for (int off = 1; off < 16; off <<= 1)
            #pragma unroll
            for (int r = 0; r < 4; r++)
                rmax[r] = fmaxf(rmax[r], __shfl_xor_sync(0xffffffffu, rmax[r], off));

        #pragma unroll
        for (int r = 0; r < 4; r++) {
            float mn = fmaxf(m[r], rmax[r]);
            float sc = __expf(m[r] - mn);
            m[r] = mn;
            #pragma unroll
            for (int c = 0; c < 4; c++) s[r][c] = __expf(s[r][c] - mn);
            rsum[r] = (s[r][0] + s[r][1]) + (s[r][2] + s[r][3]);
            l[r] *= sc;
            #pragma unroll
            for (int c = 0; c < 4; c++) o[r][c] *= sc;
        }
        #pragma unroll
        for (int off = 1; off < 16; off <<= 1)
            #pragma unroll
            for (int r = 0; r < 4; r++)
                rsum[r] += __shfl_xor_sync(0xffffffffu, rsum[r], off);
        #pragma unroll
        for (int r = 0; r < 4; r++) l[r] += rsum[r];

        #pragma unroll
        for (int r = 0; r < 4; r++)
            *(float4*)&Ps[ty * 4 + r][tx * 4] =
                make_float4(s[r][0], s[r][1], s[r][2], s[r][3]);
        __syncthreads();

        #pragma unroll 4
        for (int k0 = 0; k0 < 64; k0 += 4) {
            float p[4][4];
            #pragma unroll
            for (int r = 0; r < 4; r++)
                *(float4*)p[r] = *(const float4*)&Ps[ty * 4 + r][k0];
            #pragma unroll
            for (int kk = 0; kk < 4; kk++) {
                float v4[4];
                *(float4*)v4 = *(const float4*)&Vs[k0 + kk][tx * 4];
                #pragma unroll
                for (int r = 0; r < 4; r++)
                    #pragma unroll
                    for (int c = 0; c < 4; c++)
                        o[r][c] += p[r][kk] * v4[c];
            }
        }
    }

    float* Zg = g_Z + (size_t)(b * Sq + qb * 64) * Dm + h * Dh;
    #pragma unroll
    for (int r = 0; r < 4; r++) {
        float inv = 1.f / l[r];
        float4 v = make_float4(o[r][0] * inv, o[r][1] * inv,
                               o[r][2] * inv, o[r][3] * inv);
        *(float4*)(Zg + (size_t)(ty * 4 + r) * Dm + tx * 4) = v;
    }
}

// ---------------------------------------------------------------------------
extern "C" void kernel_launch(void* const* d_in, const int* in_sizes, int n_in,
                              void* d_out, int out_size)
{
    const float* x  = (const float*)d_in[0];
    const float* wq = (const float*)d_in[1];
    const float* bq = (const float*)d_in[2];
    const float* wk = (const float*)d_in[3];
    const float* bk = (const float*)d_in[4];
    const float* wv = (const float*)d_in[5];
    const float* bv = (const float*)d_in[6];
    const float* wo = (const float*)d_in[7];
    const float* bo = (const float*)d_in[8];
    float* out = (float*)d_out;

    cudaFuncSetAttribute(attn_kernel,
                         cudaFuncAttributeMaxDynamicSharedMemorySize, 65536);
    cudaFuncSetAttribute(hmma_gemm,
                         cudaFuncAttributeMaxDynamicSharedMemorySize, GEMM_SMEM);

    void* p;
    cudaGetSymbolAddress(&p, g_xh); __nv_bfloat16* xh = (__nv_bfloat16*)p;
    cudaGetSymbolAddress(&p, g_xl); __nv_bfloat16* xl = (__nv_bfloat16*)p;
    cudaGetSymbolAddress(&p, g_zh); __nv_bfloat16* zh = (__nv_bfloat16*)p;
    cudaGetSymbolAddress(&p, g_zl); __nv_bfloat16* zl = (__nv_bfloat16*)p;
    cudaGetSymbolAddress(&p, g_wh); __nv_bfloat16* wh = (__nv_bfloat16*)p;
    cudaGetSymbolAddress(&p, g_wl); __nv_bfloat16* wl = (__nv_bfloat16*)p;
    cudaGetSymbolAddress(&p, g_oh); __nv_bfloat16* oh = (__nv_bfloat16*)p;
    cudaGetSymbolAddress(&p, g_ol); __nv_bfloat16* ol = (__nv_bfloat16*)p;
    cudaGetSymbolAddress(&p, g_Q);  float* Qf = (float*)p;
    cudaGetSymbolAddress(&p, g_K);  float* Kf = (float*)p;
    cudaGetSymbolAddress(&p, g_V);  float* Vf = (float*)p;
    cudaGetSymbolAddress(&p, g_Z);  float* Zf = (float*)p;

    // 1. split x, transpose+split weights
    conv_split<<<(Tt * Dm / 4 + 255) / 256, 256>>>(x, xh, xl, Tt * Dm / 4);
    conv_wqkv<<<(3 * Dm * Dm + 255) / 256, 256>>>(wq, wk, wv);
    conv_wo<<<(Dm * Dm + 255) / 256, 256>>>(wo);

    // 2. QKV projection: [8192 x 1024] * [3072 x 1024]^T -> Q|K|V fp32
    hmma_gemm<<<dim3(Tt / 128, 24), 256, GEMM_SMEM>>>(
        xh, xl, wh, wl, bq, bk, bv, Qf, Kf, Vf);

    // 3. attention (SIMT fp32)
    attn_kernel<<<dim3(Sq / 64, Hh, Bsz), 256, 65536>>>();

    // 4. split z, output projection
    conv_split<<<(Tt * Dm / 4 + 255) / 256, 256>>>(Zf, zh, zl, Tt * Dm / 4);
    hmma_gemm<<<dim3(Tt / 128, 8), 256, GEMM_SMEM>>>(
        zh, zl, oh, ol, bo, bo, bo, out, out, out);
}